// round 4
// baseline (speedup 1.0000x reference)
#include <cuda_runtime.h>
#include <math.h>
#include <stdint.h>

#define NPIX 4096
#define PADW 66
#define PADN 4356
#define BATCH 2
#define CVCH 256
#define CQKCH 320
#define DPCH 64
#define NHID 128

// ---------------- scratch arena ----------------
constexpr size_t SZ_QK = (size_t)BATCH * CQKCH * NPIX;
constexpr size_t SZ_CV = (size_t)BATCH * CVCH * NPIX;
constexpr size_t SZ_DP = (size_t)BATCH * DPCH * NPIX;

constexpr size_t OFF_QUERY = 0;
constexpr size_t OFF_KEYT  = OFF_QUERY + SZ_QK;
constexpr size_t OFF_QF    = OFF_KEYT + SZ_QK;
constexpr size_t OFF_KF    = OFF_QF + SZ_QK;
constexpr size_t OFF_QP    = OFF_KF + SZ_QK;
constexpr size_t OFF_KP    = OFF_QP + SZ_DP;
constexpr size_t OFF_VH    = OFF_KP + SZ_DP;
constexpr size_t OFF_OUT   = OFF_VH + SZ_CV;
constexpr size_t OFF_STATS = OFF_OUT + SZ_CV;                  // B*N*4
constexpr size_t OFF_CONF  = OFF_STATS + (size_t)BATCH*NPIX*4; // B*N
constexpr size_t OFF_ACTV  = OFF_CONF + (size_t)BATCH*NPIX;    // B*128*PADN
constexpr size_t OFF_GAMMA = OFF_ACTV + (size_t)BATCH*NHID*PADN;
constexpr size_t OFF_BETA  = OFF_GAMMA + SZ_CV;
constexpr size_t OFF_INST  = OFF_BETA + SZ_CV;                 // B*CV*2
constexpr size_t OFF_YPRE  = OFF_INST + (size_t)BATCH*CVCH*2;
constexpr size_t OFF_PST   = OFF_YPRE + SZ_CV;                 // B*N*2
constexpr size_t OFF_YPAD  = OFF_PST + (size_t)BATCH*NPIX*2;
constexpr size_t OFF_T1PAD = OFF_YPAD + (size_t)BATCH*CVCH*PADN;
constexpr size_t OFF_SEGP  = OFF_T1PAD + (size_t)BATCH*CVCH*PADN;
constexpr size_t OFF_WT    = OFF_SEGP + 26176;  // B*3*PADN=26136, padded
// transposed weights (float offsets within OFF_WT)
constexpr size_t WT_F   = 0;
constexpr size_t WT_G   = WT_F  + 320*320;
constexpr size_t WT_H   = WT_G  + 320*320;
constexpr size_t WT_FP  = WT_H  + 256*256;
constexpr size_t WT_GP  = WT_FP + 320*64;
constexpr size_t WT_SPS = WT_GP + 320*64;
constexpr size_t WT_SPG = WT_SPS + 9*3*128;
constexpr size_t WT_SPB = WT_SPG + 9*128*256;
constexpr size_t WT_R1  = WT_SPB + 9*128*256;
constexpr size_t WT_R2  = WT_R1  + 9*256*256;
constexpr size_t WT_END = WT_R2  + 9*256*256;
constexpr size_t OFF_MASK = OFF_WT + ((WT_END + 63) & ~(size_t)63);
constexpr size_t ARENA_FLOATS = OFF_MASK + ((size_t)BATCH*NPIX*NPIX)/4 + 64;

__device__ __align__(16) float g_arena[ARENA_FLOATS];

// ---------------- utility kernels ----------------
__global__ void zero_kernel(float* p, int n){
    int i = blockIdx.x * blockDim.x + threadIdx.x;
    if (i < n) p[i] = 0.f;
}

// dst[t*K*M + k*M + m] = src[(m*K + k)*taps + t]
__global__ void transpose_w(const float* __restrict__ src, float* __restrict__ dst,
                            int M, int K, int taps){
    int idx = blockIdx.x * blockDim.x + threadIdx.x;
    if (idx >= M * K * taps) return;
    int t = idx / (K * M);
    int r = idx % (K * M);
    int k = r / M;
    int m = r % M;
    dst[idx] = src[((size_t)m * K + k) * taps + t];
}

__global__ void pad_seg(const float* __restrict__ seg, float* __restrict__ dst){
    int idx = blockIdx.x * blockDim.x + threadIdx.x;
    if (idx >= BATCH * 3 * PADN) return;
    int bc = idx / PADN;
    int r = idx % PADN;
    int yy = r / PADW, xx = r % PADW;
    float v = 0.f;
    if (yy >= 1 && yy <= 64 && xx >= 1 && xx <= 64)
        v = seg[(size_t)bc * NPIX + (yy - 1) * 64 + (xx - 1)];
    dst[idx] = v;
}

// feature_normalize + concat pos
__global__ __launch_bounds__(256) void norm_concat(
    const float* __restrict__ q, const float* __restrict__ k,
    const float* __restrict__ pos, float* __restrict__ outq, float* __restrict__ outk){
    const float* src = blockIdx.y ? k : q;
    float* dst = blockIdx.y ? outk : outq;
    int b = blockIdx.x / 64, y = blockIdx.x % 64;
    int tid = threadIdx.x;
    int x = tid & 63, cl = tid >> 6;
    const float* sb = src + (size_t)b * CVCH * NPIX + y * 64;
    __shared__ float partial[4][64];
    __shared__ float inv[64];
    float ss = 0.f;
    for (int c = cl; c < CVCH; c += 4){ float v = sb[(size_t)c * NPIX + x]; ss += v * v; }
    partial[cl][x] = ss;
    __syncthreads();
    if (cl == 0){
        float s = partial[0][x] + partial[1][x] + partial[2][x] + partial[3][x];
        inv[x] = 1.f / (sqrtf(s) + 2.220446049250313e-16f);
    }
    __syncthreads();
    float* db = dst + (size_t)b * CQKCH * NPIX + y * 64;
    float iv = inv[x];
    for (int c = cl; c < CVCH; c += 4) db[(size_t)c * NPIX + x] = sb[(size_t)c * NPIX + x] * iv;
    const float* pb = pos + y * 64;
    for (int i = tid; i < 64 * 64; i += 256){
        int cp = i >> 6, xx = i & 63;
        db[(size_t)(CVCH + cp) * NPIX + xx] = pb[(size_t)cp * NPIX + xx];
    }
}

// ------------- generic W@X GEMM (1x1 / 3x3-as-9-shifted-GEMMs) -------------
__global__ __launch_bounds__(256) void gemm_wx(
    const float* __restrict__ Wt, const float* __restrict__ X,
    const float* __restrict__ bias, float* __restrict__ Cout,
    int M, int K, int taps,
    long xBatchStride, int xChanStride, long cBatchStride,
    int relu, int outPadded,
    const float* __restrict__ addsrc, long addBatchStride)
{
    int b = blockIdx.z;
    int n0 = blockIdx.x * 64;
    int m0 = blockIdx.y * 64;
    int y = n0 >> 6;
    const float* Xb = X + (size_t)b * xBatchStride;
    __shared__ __align__(16) float As[16][64];
    __shared__ __align__(16) float Bs[16][64];
    float acc[4][4] = {};
    int tid = threadIdx.x;
    int tx = tid & 15, ty = tid >> 4;
    for (int tap = 0; tap < taps; ++tap){
        const float* Wtap = Wt + (size_t)tap * K * M + m0;
        long xbase;
        if (taps == 1) xbase = n0;
        else { int ky = tap / 3, kx = tap % 3; xbase = (long)(y + ky) * PADW + kx; }
        for (int k0 = 0; k0 < K; k0 += 16){
#pragma unroll
            for (int i = 0; i < 4; ++i){
                int idx = tid + 256 * i;
                int kk = idx >> 6, col = idx & 63;
                int kg = k0 + kk;
                float av = 0.f, bv = 0.f;
                if (kg < K){
                    av = Wtap[(size_t)kg * M + col];
                    bv = Xb[(size_t)kg * xChanStride + xbase + col];
                }
                As[kk][col] = av;
                Bs[kk][col] = bv;
            }
            __syncthreads();
#pragma unroll
            for (int kk = 0; kk < 16; ++kk){
                float4 a  = *(const float4*)&As[kk][ty * 4];
                float4 bb = *(const float4*)&Bs[kk][tx * 4];
                float av[4] = {a.x, a.y, a.z, a.w};
                float bv[4] = {bb.x, bb.y, bb.z, bb.w};
#pragma unroll
                for (int i = 0; i < 4; ++i)
#pragma unroll
                    for (int j = 0; j < 4; ++j)
                        acc[i][j] += av[i] * bv[j];
            }
            __syncthreads();
        }
    }
#pragma unroll
    for (int i = 0; i < 4; ++i){
        int m = m0 + ty * 4 + i;
        float bvv = bias ? bias[m] : 0.f;
#pragma unroll
        for (int j = 0; j < 4; ++j){
            int x = tx * 4 + j;
            float v = acc[i][j] + bvv;
            if (relu) v = fmaxf(v, 0.f);
            if (addsrc)
                v += addsrc[(size_t)b * addBatchStride + (size_t)m * PADN + (size_t)(y + 1) * PADW + x + 1];
            if (outPadded)
                Cout[(size_t)b * cBatchStride + (size_t)m * PADN + (size_t)(y + 1) * PADW + x + 1] = v;
            else
                Cout[(size_t)b * cBatchStride + (size_t)m * NPIX + n0 + x] = v;
        }
    }
}

// ---------------- cor + mask fused GEMM ----------------
__global__ __launch_bounds__(256) void gemm_corr(
    const float* __restrict__ qf, const float* __restrict__ kf,
    const float* __restrict__ qp, const float* __restrict__ kp,
    float* __restrict__ cor, unsigned char* __restrict__ mask)
{
    int b = blockIdx.z;
    int n0 = blockIdx.y * 64, m0 = blockIdx.x * 64;
    __shared__ __align__(16) float As[16][64];
    __shared__ __align__(16) float Bs[16][64];
    int tid = threadIdx.x, tx = tid & 15, ty = tid >> 4;
    float acc[4][4] = {};
    const float* A  = qf + (size_t)b * CQKCH * NPIX + n0;
    const float* Bm = kf + (size_t)b * CQKCH * NPIX + m0;
    for (int k0 = 0; k0 < CQKCH; k0 += 16){
#pragma unroll
        for (int i = 0; i < 4; ++i){
            int idx = tid + 256 * i;
            int kk = idx >> 6, col = idx & 63;
            As[kk][col] = A [(size_t)(k0 + kk) * NPIX + col];
            Bs[kk][col] = Bm[(size_t)(k0 + kk) * NPIX + col];
        }
        __syncthreads();
#pragma unroll
        for (int kk = 0; kk < 16; ++kk){
            float4 a  = *(const float4*)&As[kk][ty * 4];
            float4 bb = *(const float4*)&Bs[kk][tx * 4];
            float av[4] = {a.x, a.y, a.z, a.w};
            float bv[4] = {bb.x, bb.y, bb.z, bb.w};
#pragma unroll
            for (int i = 0; i < 4; ++i)
#pragma unroll
                for (int j = 0; j < 4; ++j)
                    acc[i][j] += av[i] * bv[j];
        }
        __syncthreads();
    }
    const float scale = rsqrtf((float)CQKCH);
    size_t corBase = (size_t)b * NPIX * NPIX;
#pragma unroll
    for (int i = 0; i < 4; ++i){
        int n = n0 + ty * 4 + i;
        float4 v;
        v.x = acc[i][0] * scale; v.y = acc[i][1] * scale;
        v.z = acc[i][2] * scale; v.w = acc[i][3] * scale;
        *(float4*)&cor[corBase + (size_t)n * NPIX + m0 + tx * 4] = v;
    }
    // mask pass (K = 64)
    float acc2[4][4] = {};
    const float* Ap = qp + (size_t)b * DPCH * NPIX + n0;
    const float* Bp = kp + (size_t)b * DPCH * NPIX + m0;
    for (int k0 = 0; k0 < DPCH; k0 += 16){
#pragma unroll
        for (int i = 0; i < 4; ++i){
            int idx = tid + 256 * i;
            int kk = idx >> 6, col = idx & 63;
            As[kk][col] = Ap[(size_t)(k0 + kk) * NPIX + col];
            Bs[kk][col] = Bp[(size_t)(k0 + kk) * NPIX + col];
        }
        __syncthreads();
#pragma unroll
        for (int kk = 0; kk < 16; ++kk){
            float4 a  = *(const float4*)&As[kk][ty * 4];
            float4 bb = *(const float4*)&Bs[kk][tx * 4];
            float av[4] = {a.x, a.y, a.z, a.w};
            float bv[4] = {bb.x, bb.y, bb.z, bb.w};
#pragma unroll
            for (int i = 0; i < 4; ++i)
#pragma unroll
                for (int j = 0; j < 4; ++j)
                    acc2[i][j] += av[i] * bv[j];
        }
        __syncthreads();
    }
#pragma unroll
    for (int i = 0; i < 4; ++i){
        int n = n0 + ty * 4 + i;
#pragma unroll
        for (int j = 0; j < 4; ++j)
            mask[corBase + (size_t)n * NPIX + m0 + tx * 4 + j] = (acc2[i][j] > 0.f) ? 1 : 0;
    }
}

// -------- per-row softmax stats for both variants + conf --------
__global__ __launch_bounds__(256) void row_stats(
    const float* __restrict__ cor, const unsigned char* __restrict__ mask,
    float* __restrict__ stats, float* __restrict__ conf)
{
    int b = blockIdx.y, n = blockIdx.x;
    const float* row = cor + ((size_t)b * NPIX + n) * NPIX;
    const unsigned char* mrow = mask + ((size_t)b * NPIX + n) * NPIX;
    int t = threadIdx.x;
    float m1 = -1e30f, m2 = -1e30f;
    for (int i = t; i < NPIX; i += 256){
        float s = row[i];
        m1 = fmaxf(m1, s);
        m2 = fmaxf(m2, mrow[i] ? -10000.f : s);
    }
    __shared__ float r1[256], r2[256], r3[256];
    r1[t] = m1; r2[t] = m2;
    __syncthreads();
    for (int o = 128; o > 0; o >>= 1){
        if (t < o){ r1[t] = fmaxf(r1[t], r1[t + o]); r2[t] = fmaxf(r2[t], r2[t + o]); }
        __syncthreads();
    }
    float M1 = r1[0], M2 = r2[0];
    __syncthreads();
    float d1 = 0.f, num = 0.f, d2 = 0.f;
    for (int i = t; i < NPIX; i += 256){
        float s = row[i];
        int mk = mrow[i];
        float e1 = __expf(s - M1);
        d1 += e1;
        num += mk ? e1 : 0.f;
        d2 += __expf((mk ? -10000.f : s) - M2);
    }
    r1[t] = d1; r2[t] = num; r3[t] = d2;
    __syncthreads();
    for (int o = 128; o > 0; o >>= 1){
        if (t < o){ r1[t] += r1[t + o]; r2[t] += r2[t + o]; r3[t] += r3[t + o]; }
        __syncthreads();
    }
    if (t == 0){
        float* st = stats + ((size_t)b * NPIX + n) * 4;
        st[0] = M1; st[1] = r1[0]; st[2] = M2; st[3] = r3[0];
        conf[(size_t)b * NPIX + n] = r2[0] / r1[0];
    }
}

// -------- fused attention: out = (attn*mask)@V, out2 = attn2@V2 --------
__global__ __launch_bounds__(256) void attn_out(
    const float* __restrict__ cor, const unsigned char* __restrict__ mask,
    const float* __restrict__ stats, const float* __restrict__ vh,
    const float* __restrict__ v2, float* __restrict__ out, float* __restrict__ out2)
{
    int b = blockIdx.z;
    int n0 = blockIdx.x * 64;
    int c0 = blockIdx.y * 64;
    __shared__ __align__(16) float V1s[16][68], V2s[16][68], P1[16][68], P2[16][68];
    __shared__ float sM1[64], sD1[64], sM2[64], sD2[64];
    int tid = threadIdx.x, tx = tid & 15, ty = tid >> 4;
    if (tid < 64){
        const float* st = stats + ((size_t)b * NPIX + n0 + tid) * 4;
        sM1[tid] = st[0]; sD1[tid] = 1.f / st[1];
        sM2[tid] = st[2]; sD2[tid] = 1.f / st[3];
    }
    __syncthreads();
    float acc1[4][4] = {}, acc2[4][4] = {};
    const float* vhb = vh + (size_t)b * CVCH * NPIX;
    const float* v2b = v2 + (size_t)b * CVCH * NPIX;
    const float* corb = cor + (size_t)b * NPIX * NPIX;
    const unsigned char* mb = mask + (size_t)b * NPIX * NPIX;
    for (int m0 = 0; m0 < NPIX; m0 += 16){
#pragma unroll
        for (int i = 0; i < 4; ++i){
            int idx = tid + 256 * i;
            int kk = idx & 15, r = idx >> 4;
            V1s[kk][r] = vhb[(size_t)(c0 + r) * NPIX + m0 + kk];
            V2s[kk][r] = v2b[(size_t)(c0 + r) * NPIX + m0 + kk];
            float s = corb[(size_t)(n0 + r) * NPIX + m0 + kk];
            int mk = mb[(size_t)(n0 + r) * NPIX + m0 + kk];
            float e1 = __expf(s - sM1[r]);
            P1[kk][r] = mk ? e1 * sD1[r] : 0.f;
            float e2 = __expf((mk ? -10000.f : s) - sM2[r]);
            P2[kk][r] = e2 * sD2[r];
        }
        __syncthreads();
#pragma unroll
        for (int kk = 0; kk < 16; ++kk){
            float4 p1 = *(const float4*)&P1[kk][ty * 4];
            float4 p2 = *(const float4*)&P2[kk][ty * 4];
            float4 w1 = *(const float4*)&V1s[kk][tx * 4];
            float4 w2 = *(const float4*)&V2s[kk][tx * 4];
            float pa1[4] = {p1.x, p1.y, p1.z, p1.w}, pa2[4] = {p2.x, p2.y, p2.z, p2.w};
            float wa1[4] = {w1.x, w1.y, w1.z, w1.w}, wa2[4] = {w2.x, w2.y, w2.z, w2.w};
#pragma unroll
            for (int i = 0; i < 4; ++i)
#pragma unroll
                for (int j = 0; j < 4; ++j){
                    acc1[i][j] += pa1[i] * wa1[j];
                    acc2[i][j] += pa2[i] * wa2[j];
                }
        }
        __syncthreads();
    }
#pragma unroll
    for (int j = 0; j < 4; ++j){
        int c = c0 + tx * 4 + j;
        float4 v1, v2o;
        v1.x = acc1[0][j]; v1.y = acc1[1][j]; v1.z = acc1[2][j]; v1.w = acc1[3][j];
        v2o.x = acc2[0][j]; v2o.y = acc2[1][j]; v2o.z = acc2[2][j]; v2o.w = acc2[3][j];
        *(float4*)&out [(size_t)b * CVCH * NPIX + (size_t)c * NPIX + n0 + ty * 4] = v1;
        *(float4*)&out2[(size_t)b * CVCH * NPIX + (size_t)c * NPIX + n0 + ty * 4] = v2o;
    }
}

// -------- instance-norm stats of q --------
__global__ void inorm_stats(const float* __restrict__ q, float* __restrict__ inst){
    int bc = blockIdx.x;
    const float* p = q + (size_t)bc * NPIX;
    int t = threadIdx.x;
    float s = 0.f, ss = 0.f;
    for (int i = t; i < NPIX; i += 256){ float v = p[i]; s += v; ss += v * v; }
    __shared__ float rs[256], rss[256];
    rs[t] = s; rss[t] = ss;
    __syncthreads();
    for (int o = 128; o > 0; o >>= 1){
        if (t < o){ rs[t] += rs[t + o]; rss[t] += rss[t + o]; }
        __syncthreads();
    }
    if (t == 0){
        float m = rs[0] / NPIX;
        float var = rss[0] / NPIX - m * m;
        inst[bc * 2] = m;
        inst[bc * 2 + 1] = rsqrtf(var + 1e-5f);
    }
}

// -------- fuse: ypre = out + (1-conf)*spade + q; pono stats --------
__global__ __launch_bounds__(256) void fuse1(
    const float* __restrict__ outb, const float* __restrict__ q,
    const float* __restrict__ gamma, const float* __restrict__ beta,
    const float* __restrict__ inst, const float* __restrict__ conf,
    float* __restrict__ ypre, float* __restrict__ pst)
{
    int b = blockIdx.x >> 6, y = blockIdx.x & 63;
    int tid = threadIdx.x;
    int x = tid & 63, cl = tid >> 6;
    int n = y * 64 + x;
    float one_m = 1.f - conf[(size_t)b * NPIX + n];
    size_t base = (size_t)b * CVCH * NPIX + n;
    float s = 0.f, ss = 0.f;
    for (int c = cl; c < CVCH; c += 4){
        size_t o = base + (size_t)c * NPIX;
        float qq = q[o];
        float im = inst[((size_t)b * CVCH + c) * 2];
        float is = inst[((size_t)b * CVCH + c) * 2 + 1];
        float sp = (qq - im) * is * (1.f + gamma[o]) + beta[o];
        float v = outb[o] + one_m * sp + qq;
        ypre[o] = v;
        s += v; ss += v * v;
    }
    __shared__ float rs[4][64], rss[4][64];
    rs[cl][x] = s; rss[cl][x] = ss;
    __syncthreads();
    if (cl == 0){
        float S  = rs[0][x] + rs[1][x] + rs[2][x] + rs[3][x];
        float SS = rss[0][x] + rss[1][x] + rss[2][x] + rss[3][x];
        float m = S / 256.f;
        float var = SS / 256.f - m * m;
        pst[((size_t)b * NPIX + n) * 2] = m;
        pst[((size_t)b * NPIX + n) * 2 + 1] = rsqrtf(var + 1e-5f);
    }
}

// -------- pono-normalize + write padded --------
__global__ void fuse2(const float* __restrict__ ypre, const float* __restrict__ pst,
                      float* __restrict__ ypad){
    int idx = blockIdx.x * blockDim.x + threadIdx.x;
    if (idx >= BATCH * CVCH * NPIX) return;
    int n = idx & (NPIX - 1);
    int c = (idx >> 12) & 255;
    int b = idx >> 20;
    float m  = pst[((size_t)b * NPIX + n) * 2];
    float is = pst[((size_t)b * NPIX + n) * 2 + 1];
    int yy = n >> 6, xx = n & 63;
    ypad[(size_t)b * CVCH * PADN + (size_t)c * PADN + (size_t)(yy + 1) * PADW + xx + 1]
        = (ypre[idx] - m) * is;
}

extern "C" void kernel_launch(void* const* d_in, const int* in_sizes, int n_in,
                              void* d_out, int out_size){
    float* arena = nullptr;
    cudaGetSymbolAddress((void**)&arena, g_arena);

    const float* q    = (const float*)d_in[0];
    const float* k    = (const float*)d_in[1];
    const float* v    = (const float*)d_in[2];
    const float* pos  = (const float*)d_in[3];
    const float* v2   = (const float*)d_in[5];

    float* res  = (float*)d_out;
    float* out2 = res + (size_t)BATCH * CVCH * NPIX;
    float* cor  = out2 + (size_t)BATCH * CVCH * NPIX;

    float* QUERY = arena + OFF_QUERY;
    float* KEYT  = arena + OFF_KEYT;
    float* QF    = arena + OFF_QF;
    float* KF    = arena + OFF_KF;
    float* QP    = arena + OFF_QP;
    float* KP    = arena + OFF_KP;
    float* VH    = arena + OFF_VH;
    float* OUTB  = arena + OFF_OUT;
    float* STATS = arena + OFF_STATS;
    float* CONF  = arena + OFF_CONF;
    float* ACTV  = arena + OFF_ACTV;
    float* GAMMA = arena + OFF_GAMMA;
    float* BETA  = arena + OFF_BETA;
    float* INST  = arena + OFF_INST;
    float* YPRE  = arena + OFF_YPRE;
    float* PST   = arena + OFF_PST;
    float* YPAD  = arena + OFF_YPAD;
    float* T1PAD = arena + OFF_T1PAD;
    float* SEGP  = arena + OFF_SEGP;
    float* WT    = arena + OFF_WT;
    unsigned char* MASK = (unsigned char*)(arena + OFF_MASK);

    // weight transposes
    auto T = [&](int si, size_t off, int M, int K, int taps){
        int tot = M * K * taps;
        transpose_w<<<(tot + 255) / 256, 256>>>((const float*)d_in[si], WT + off, M, K, taps);
    };
    T(6,  WT_F,   320, 320, 1);
    T(8,  WT_G,   320, 320, 1);
    T(10, WT_H,   256, 256, 1);
    T(12, WT_FP,  64,  320, 1);
    T(14, WT_GP,  64,  320, 1);
    T(16, WT_SPS, 128, 3,   9);
    T(18, WT_SPG, 256, 128, 9);
    T(20, WT_SPB, 256, 128, 9);
    T(22, WT_R1,  256, 256, 9);
    T(24, WT_R2,  256, 256, 9);

    pad_seg<<<(BATCH * 3 * PADN + 255) / 256, 256>>>((const float*)d_in[4], SEGP);
    norm_concat<<<dim3(BATCH * 64, 2), 256>>>(q, k, pos, QUERY, KEYT);

    long sQK = (long)CQKCH * NPIX, sCV = (long)CVCH * NPIX, sDP = (long)DPCH * NPIX;
    // 1x1 convs
    gemm_wx<<<dim3(64, 5, 2), 256>>>(WT + WT_F,  QUERY, (const float*)d_in[7],  QF, 320, 320, 1, sQK, NPIX, sQK, 0, 0, nullptr, 0);
    gemm_wx<<<dim3(64, 5, 2), 256>>>(WT + WT_G,  KEYT,  (const float*)d_in[9],  KF, 320, 320, 1, sQK, NPIX, sQK, 0, 0, nullptr, 0);
    gemm_wx<<<dim3(64, 4, 2), 256>>>(WT + WT_H,  v,     (const float*)d_in[11], VH, 256, 256, 1, sCV, NPIX, sCV, 0, 0, nullptr, 0);
    gemm_wx<<<dim3(64, 1, 2), 256>>>(WT + WT_FP, QUERY, (const float*)d_in[13], QP, 64,  320, 1, sQK, NPIX, sDP, 0, 0, nullptr, 0);
    gemm_wx<<<dim3(64, 1, 2), 256>>>(WT + WT_GP, KEYT,  (const float*)d_in[15], KP, 64,  320, 1, sQK, NPIX, sDP, 0, 0, nullptr, 0);

    gemm_corr<<<dim3(64, 64, 2), 256>>>(QF, KF, QP, KP, cor, MASK);
    row_stats<<<dim3(NPIX, BATCH), 256>>>(cor, MASK, STATS, CONF);
    attn_out<<<dim3(64, 4, 2), 256>>>(cor, MASK, STATS, VH, v2, OUTB, out2);

    // SPADE path
    int nACTV = BATCH * NHID * PADN, nPAD = BATCH * CVCH * PADN;
    zero_kernel<<<(nACTV + 255) / 256, 256>>>(ACTV, nACTV);
    zero_kernel<<<(nPAD + 255) / 256, 256>>>(YPAD, nPAD);
    zero_kernel<<<(nPAD + 255) / 256, 256>>>(T1PAD, nPAD);

    gemm_wx<<<dim3(64, 2, 2), 256>>>(WT + WT_SPS, SEGP, (const float*)d_in[17], ACTV, 128, 3,   9, (long)3 * PADN,    PADN, (long)NHID * PADN, 1, 1, nullptr, 0);
    gemm_wx<<<dim3(64, 4, 2), 256>>>(WT + WT_SPG, ACTV, (const float*)d_in[19], GAMMA, 256, 128, 9, (long)NHID * PADN, PADN, sCV, 0, 0, nullptr, 0);
    gemm_wx<<<dim3(64, 4, 2), 256>>>(WT + WT_SPB, ACTV, (const float*)d_in[21], BETA,  256, 128, 9, (long)NHID * PADN, PADN, sCV, 0, 0, nullptr, 0);

    inorm_stats<<<BATCH * CVCH, 256>>>(q, INST);
    fuse1<<<BATCH * 64, 256>>>(OUTB, q, GAMMA, BETA, INST, CONF, YPRE, PST);
    fuse2<<<(BATCH * CVCH * NPIX + 255) / 256, 256>>>(YPRE, PST, YPAD);

    gemm_wx<<<dim3(64, 4, 2), 256>>>(WT + WT_R1, YPAD,  (const float*)d_in[23], T1PAD, 256, 256, 9, (long)CVCH * PADN, PADN, (long)CVCH * PADN, 1, 1, nullptr, 0);
    gemm_wx<<<dim3(64, 4, 2), 256>>>(WT + WT_R2, T1PAD, (const float*)d_in[25], res,   256, 256, 9, (long)CVCH * PADN, PADN, sCV, 0, 0, YPAD, (long)CVCH * PADN);
}